// round 1
// baseline (speedup 1.0000x reference)
#include <cuda_runtime.h>
#include <cuda_bf16.h>
#include <math.h>

#define NN 10000          // nodes
#define NE 50000          // edges
#define IN_CH 32
#define EIN 16            // edge_attr dim
#define GIN 8
#define HID 64
#define NG 64             // graphs
#define QW 8192           // Q row width = 128*64
#define EPS_BN 1e-5f

// ---------------- device scratch (no allocation allowed) ----------------
__device__ float g_Wp[64 * QW];           // permuted W2 (max K=64)  2 MB
__device__ float g_H [(size_t)NE * 128];  // edge hidden            25.6 MB
__device__ float g_Q [(size_t)NN * QW];   // per-node Q             327 MB
__device__ float g_xA[NN * HID];
__device__ float g_xB[NN * HID];
__device__ float g_agg[NN * HID];
__device__ float g_xb [NN * HID];
__device__ int   g_cnt[NN];
__device__ int   g_off[NN + 1];
__device__ int   g_cur[NN];
__device__ int   g_perm[NE];
__device__ float g_bnsum[HID];
__device__ float g_bnsq [HID];
__device__ float g_pool[NG * HID];

// ---------------- CSR build (group edges by src) ----------------
__global__ void k_zero_cnt() {
    int i = blockIdx.x * blockDim.x + threadIdx.x;
    if (i < NN) g_cnt[i] = 0;
}
__global__ void k_count(const int* __restrict__ src) {
    int e = blockIdx.x * blockDim.x + threadIdx.x;
    if (e < NE) atomicAdd(&g_cnt[src[e]], 1);
}
__global__ void k_scan() {   // single block, 1024 threads
    __shared__ int part[1024];
    int t = threadIdx.x;
    const int CH = (NN + 1023) / 1024;  // 10
    int base = t * CH;
    int s = 0;
    for (int i = 0; i < CH; i++) {
        int idx = base + i;
        if (idx < NN) s += g_cnt[idx];
    }
    part[t] = s;
    __syncthreads();
    for (int d = 1; d < 1024; d <<= 1) {
        int v = (t >= d) ? part[t - d] : 0;
        __syncthreads();
        part[t] += v;
        __syncthreads();
    }
    int pre = (t == 0) ? 0 : part[t - 1];
    for (int i = 0; i < CH; i++) {
        int idx = base + i;
        if (idx < NN) {
            g_off[idx] = pre;
            g_cur[idx] = pre;
            pre += g_cnt[idx];
        }
    }
    if (t == 1023) g_off[NN] = part[1023];
}
__global__ void k_scatter(const int* __restrict__ src) {
    int e = blockIdx.x * blockDim.x + threadIdx.x;
    if (e < NE) {
        int p = atomicAdd(&g_cur[src[e]], 1);
        g_perm[p] = e;
    }
}

// ---------------- W2 permute: Wp[k, c*64+o] = w2[c, k*64+o] ----------------
__global__ void k_permute(const float* __restrict__ w2, int C) {
    int p = blockIdx.x * blockDim.x + threadIdx.x;
    int total = 128 * C * 64;
    if (p >= total) return;
    int k = p / QW;
    int rem = p - k * QW;
    int c = rem >> 6;
    int o = rem & 63;
    g_Wp[p] = w2[(size_t)c * C * 64 + k * 64 + o];
}

// ---------------- edge hidden: H[e,c] = relu(ea @ w1 + b1) ----------------
#define EPC 25
__global__ void k_edge_h(const float* __restrict__ ea,
                         const float* __restrict__ w1,
                         const float* __restrict__ b1) {
    __shared__ float ws[EIN * 128];
    __shared__ float bs[128];
    __shared__ float eas[EIN];
    int c = threadIdx.x;  // 128
    for (int i = 0; i < EIN; i++) ws[i * 128 + c] = w1[i * 128 + c];
    bs[c] = b1[c];
    int e0 = blockIdx.x * EPC;
    int e1 = min(e0 + EPC, NE);
    for (int e = e0; e < e1; e++) {
        __syncthreads();
        if (c < EIN) eas[c] = ea[(size_t)e * EIN + c];
        __syncthreads();
        float s = bs[c];
#pragma unroll
        for (int i = 0; i < EIN; i++) s += eas[i] * ws[i * 128 + c];
        g_H[(size_t)e * 128 + c] = fmaxf(s, 0.f);
    }
}

// ---------------- node pre: agg = x@root + bias ; xb = x@b2resh ----------------
__global__ void k_node_pre(const float* __restrict__ x, int C,
                           const float* __restrict__ root,
                           const float* __restrict__ bias,
                           const float* __restrict__ b2) {
    __shared__ float xs[4][64];
    __shared__ float rs[64 * 64];
    __shared__ float b2s[64 * 64];
    int t = threadIdx.x;      // 256
    int o = t & 63, s = t >> 6;
    for (int i = t; i < C * 64; i += 256) { rs[i] = root[i]; b2s[i] = b2[i]; }
    int n = blockIdx.x * 4 + s;
    if (n < NN) for (int k = o; k < C; k += 64) xs[s][k] = x[(size_t)n * C + k];
    __syncthreads();
    if (n < NN) {
        float a = bias[o], xbv = 0.f;
        for (int k = 0; k < C; k++) {
            float xv = xs[s][k];
            a   += xv * rs [k * 64 + o];
            xbv += xv * b2s[k * 64 + o];
        }
        g_agg[n * 64 + o] = a;
        g_xb [n * 64 + o] = xbv;
    }
}

// ---------------- Q GEMM: Q[n,j] = sum_k X[n,k]*Wp[k,j] ----------------
// CTA: 256 thr, tile 64 rows x 128 cols, thread = 4x8 microtile
__global__ void k_qgemm(const float* __restrict__ X, int K) {
    __shared__ float Xs[64][17];
    __shared__ float Ws[16][128];
    int tid = threadIdx.x;
    int tcol = tid & 15;      // 16 col groups of 8
    int trow = tid >> 4;      // 16 row groups of 4
    int row0 = blockIdx.y * 64;
    int col0 = blockIdx.x * 128;
    float acc[4][8];
#pragma unroll
    for (int i = 0; i < 4; i++)
#pragma unroll
        for (int j = 0; j < 8; j++) acc[i][j] = 0.f;

    for (int kc = 0; kc < K; kc += 16) {
        for (int i = tid; i < 64 * 16; i += 256) {
            int r = i >> 4, k = i & 15;
            int n = row0 + r;
            Xs[r][k] = (n < NN) ? X[(size_t)n * K + kc + k] : 0.f;
        }
        for (int i = tid; i < 16 * 128; i += 256) {
            int k = i >> 7, c = i & 127;
            Ws[k][c] = g_Wp[(size_t)(kc + k) * QW + col0 + c];
        }
        __syncthreads();
#pragma unroll
        for (int k = 0; k < 16; k++) {
            float a[4];
#pragma unroll
            for (int i = 0; i < 4; i++) a[i] = Xs[trow * 4 + i][k];
            float4 b0 = *reinterpret_cast<const float4*>(&Ws[k][tcol * 8]);
            float4 b1 = *reinterpret_cast<const float4*>(&Ws[k][tcol * 8 + 4]);
            float b[8] = {b0.x, b0.y, b0.z, b0.w, b1.x, b1.y, b1.z, b1.w};
#pragma unroll
            for (int i = 0; i < 4; i++)
#pragma unroll
                for (int j = 0; j < 8; j++) acc[i][j] += a[i] * b[j];
        }
        __syncthreads();
    }
#pragma unroll
    for (int i = 0; i < 4; i++) {
        int n = row0 + trow * 4 + i;
        if (n < NN) {
            float4 v0 = make_float4(acc[i][0], acc[i][1], acc[i][2], acc[i][3]);
            float4 v1 = make_float4(acc[i][4], acc[i][5], acc[i][6], acc[i][7]);
            float* dst = &g_Q[(size_t)n * QW + col0 + tcol * 8];
            *reinterpret_cast<float4*>(dst)     = v0;
            *reinterpret_cast<float4*>(dst + 4) = v1;
        }
    }
}

// ---------------- edge messages: msg_e = h_e^T Q[src] + xb[src]; scatter-add to dst ----------------
__global__ void k_edge_msg(const int* __restrict__ dst) {
    int n = blockIdx.x;
    int e0 = g_off[n], e1 = g_off[n + 1];
    if (e0 >= e1) return;
    int t = threadIdx.x;          // 128
    int o = t & 63, slot = t >> 6;
    __shared__ float Qs[QW];
    __shared__ float hs[2][128];
    __shared__ float xbs[64];
    for (int i = t; i < QW; i += 128) Qs[i] = g_Q[(size_t)n * QW + i];
    if (t < 64) xbs[t] = g_xb[n * 64 + t];
    for (int ei = e0; ei < e1; ei += 2) {
        int myei = ei + slot;
        int e = (myei < e1) ? g_perm[myei] : -1;
        __syncthreads();
        if (e >= 0) {
            hs[slot][o]      = g_H[(size_t)e * 128 + o];
            hs[slot][64 + o] = g_H[(size_t)e * 128 + 64 + o];
        }
        __syncthreads();
        if (e >= 0) {
            float m = xbs[o];
#pragma unroll
            for (int c = 0; c < 128; c++) m += hs[slot][c] * Qs[c * 64 + o];
            atomicAdd(&g_agg[(size_t)dst[e] * 64 + o], m);
        }
    }
}

// ---------------- batch norm ----------------
__global__ void k_bn_zero() {
    int t = threadIdx.x;
    if (t < HID) { g_bnsum[t] = 0.f; g_bnsq[t] = 0.f; }
}
__global__ void k_bn_stats() {
    int t = threadIdx.x;              // 256
    int o = t & 63, s = t >> 6;
    float sum = 0.f, sq = 0.f;
    for (int n = blockIdx.x * 4 + s; n < NN; n += gridDim.x * 4) {
        float v = g_agg[(size_t)n * 64 + o];
        sum += v; sq += v * v;
    }
    __shared__ float ssum[256], ssq[256];
    ssum[t] = sum; ssq[t] = sq;
    __syncthreads();
    if (t < 128) { ssum[t] += ssum[t + 128]; ssq[t] += ssq[t + 128]; }
    __syncthreads();
    if (t < 64) {
        atomicAdd(&g_bnsum[t], ssum[t] + ssum[t + 64]);
        atomicAdd(&g_bnsq [t], ssq [t] + ssq [t + 64]);
    }
}
__global__ void k_bn_apply(const float* __restrict__ gamma,
                           const float* __restrict__ beta,
                           float* __restrict__ xout) {
    int i = blockIdx.x * blockDim.x + threadIdx.x;
    if (i >= NN * 64) return;
    int o = i & 63;
    float mu  = g_bnsum[o] * (1.f / NN);
    float var = g_bnsq[o] * (1.f / NN) - mu * mu;
    float v = gamma[o] * (g_agg[i] - mu) * rsqrtf(var + EPS_BN) + beta[o];
    xout[i] = fmaxf(v, 0.f);
}

// ---------------- pooling + final MLP ----------------
__global__ void k_pool_init() {
    int i = blockIdx.x * blockDim.x + threadIdx.x;
    if (i < NG * HID) g_pool[i] = 0.f;  // values are >=0 post-relu
}
__global__ void k_pool(const float* __restrict__ xl, const int* __restrict__ batch) {
    int i = blockIdx.x * blockDim.x + threadIdx.x;
    if (i >= NN * 64) return;
    int n = i >> 6, o = i & 63;
    int g = batch[n];
    atomicMax(reinterpret_cast<unsigned*>(&g_pool[g * 64 + o]),
              __float_as_uint(xl[i]));
}
__global__ void k_final(const float* __restrict__ u,
                        const float* __restrict__ w1, const float* __restrict__ b1,
                        const float* __restrict__ w2, const float* __restrict__ b2,
                        float* __restrict__ out) {
    int g = blockIdx.x;
    int j = threadIdx.x;  // 64
    __shared__ float cat[72];
    __shared__ float red[64];
    if (j < 64) cat[j] = g_pool[g * 64 + j];
    if (j < 8)  cat[64 + j] = u[g * 8 + j];
    __syncthreads();
    float h = b1[j];
#pragma unroll
    for (int k = 0; k < 72; k++) h += cat[k] * w1[k * 64 + j];
    h = fmaxf(h, 0.f);
    red[j] = h * w2[j];
    __syncthreads();
    for (int s = 32; s > 0; s >>= 1) {
        if (j < s) red[j] += red[j + s];
        __syncthreads();
    }
    if (j == 0) out[g] = red[0] + b2[0];
}

// ---------------- host ----------------
extern "C" void kernel_launch(void* const* d_in, const int* in_sizes, int n_in,
                              void* d_out, int out_size) {
    const float* x       = (const float*)d_in[0];
    const int*   ei      = (const int*)  d_in[1];
    const float* ea      = (const float*)d_in[2];
    const int*   batch   = (const int*)  d_in[3];
    const float* u       = (const float*)d_in[4];
    const float* enn0_w1 = (const float*)d_in[5];
    const float* enn0_b1 = (const float*)d_in[6];
    const float* enn0_w2 = (const float*)d_in[7];
    const float* enn0_b2 = (const float*)d_in[8];
    const float* root0   = (const float*)d_in[9];
    const float* bias0   = (const float*)d_in[10];
    const float* gamma0  = (const float*)d_in[11];
    const float* beta0   = (const float*)d_in[12];
    const float* enn_w1  = (const float*)d_in[13];
    const float* enn_b1  = (const float*)d_in[14];
    const float* enn_w2  = (const float*)d_in[15];
    const float* enn_b2  = (const float*)d_in[16];
    const float* root_l  = (const float*)d_in[17];
    const float* bias_l  = (const float*)d_in[18];
    const float* gamma_l = (const float*)d_in[19];
    const float* beta_l  = (const float*)d_in[20];
    const float* pp_w1   = (const float*)d_in[21];
    const float* pp_b1   = (const float*)d_in[22];
    const float* pp_w2   = (const float*)d_in[23];
    const float* pp_b2   = (const float*)d_in[24];

    const int* src = ei;
    const int* dst = ei + NE;

    void* pA; cudaGetSymbolAddress(&pA, g_xA);
    void* pB; cudaGetSymbolAddress(&pB, g_xB);
    float* xA = (float*)pA;
    float* xB = (float*)pB;

    // CSR by src (edges static across layers)
    k_zero_cnt<<<(NN + 255) / 256, 256>>>();
    k_count  <<<(NE + 255) / 256, 256>>>(src);
    k_scan   <<<1, 1024>>>();
    k_scatter<<<(NE + 255) / 256, 256>>>(src);

    const float* xin = x;
    int C = IN_CH;
    float* xout = xA;

    for (int l = 0; l < 4; l++) {
        const float *w1, *b1, *w2, *b2, *rt, *bs, *gm, *bt;
        if (l == 0) {
            w1 = enn0_w1; b1 = enn0_b1; w2 = enn0_w2; b2 = enn0_b2;
            rt = root0; bs = bias0; gm = gamma0; bt = beta0;
        } else {
            int m = l - 1;
            w1 = enn_w1 + (size_t)m * EIN * 128;
            b1 = enn_b1 + (size_t)m * 128;
            w2 = enn_w2 + (size_t)m * 128 * 4096;
            b2 = enn_b2 + (size_t)m * 4096;
            rt = root_l + (size_t)m * 64 * 64;
            bs = bias_l + (size_t)m * 64;
            gm = gamma_l + (size_t)m * 64;
            bt = beta_l + (size_t)m * 64;
        }
        int ptot = 128 * C * 64;
        k_permute <<<(ptot + 255) / 256, 256>>>(w2, C);
        k_edge_h  <<<(NE + EPC - 1) / EPC, 128>>>(ea, w1, b1);
        k_node_pre<<<(NN + 3) / 4, 256>>>(xin, C, rt, bs, b2);
        dim3 gq(QW / 128, (NN + 63) / 64);
        k_qgemm   <<<gq, 256>>>(xin, C);
        k_edge_msg<<<NN, 128>>>(dst);
        k_bn_zero <<<1, 64>>>();
        k_bn_stats<<<128, 256>>>();
        k_bn_apply<<<(NN * 64 + 255) / 256, 256>>>(gm, bt, xout);

        xin = xout;
        C = HID;
        xout = (xout == xA) ? xB : xA;
    }

    k_pool_init<<<(NG * HID + 255) / 256, 256>>>();
    k_pool     <<<(NN * 64 + 255) / 256, 256>>>(xin, batch);
    k_final    <<<NG, 64>>>(u, pp_w1, pp_b1, pp_w2, pp_b2, (float*)d_out);
}

// round 5
// speedup vs baseline: 1.0922x; 1.0922x over previous
#include <cuda_runtime.h>
#include <cuda_bf16.h>
#include <math.h>

typedef unsigned int u32;
typedef unsigned long long u64;

#define NN 10000
#define NE 50000
#define IN_CH 32
#define EIN 16
#define GIN 8
#define HID 64
#define NG 64
#define QW 8192
#define EPS_BN 1e-5f

// ---------------- device scratch ----------------
__device__ __nv_bfloat16 g_Wbf[8192 * 192];   // [n=8192][k'=192]: blocks hi | lo | hi
__device__ float g_H [(size_t)NE * 128];
__device__ float g_Q [(size_t)NN * QW];
__device__ float g_xA[NN * HID];
__device__ float g_xB[NN * HID];
__device__ float g_agg[NN * HID];
__device__ float g_xb [NN * HID];
__device__ int   g_cnt[NN];
__device__ int   g_off[NN + 1];
__device__ int   g_cur[NN];
__device__ int   g_perm[NE];
__device__ float g_bnsum[HID];
__device__ float g_bnsq [HID];
__device__ float g_pool[NG * HID];

// ---------------- PTX helpers (sm_80+ baseline: ldmatrix + mma.sync) ----------------
__device__ __forceinline__ u32 smem_u32(const void* p) {
    u32 a;
    asm("{ .reg .u64 t; cvta.to.shared.u64 t, %1; cvt.u32.u64 %0, t; }" : "=r"(a) : "l"(p));
    return a;
}
__device__ __forceinline__ void ldsm_x4(u32& r0, u32& r1, u32& r2, u32& r3, u32 addr) {
    asm volatile("ldmatrix.sync.aligned.m8n8.x4.shared.b16 {%0,%1,%2,%3}, [%4];"
                 : "=r"(r0), "=r"(r1), "=r"(r2), "=r"(r3) : "r"(addr));
}
__device__ __forceinline__ void ldsm_x2(u32& r0, u32& r1, u32 addr) {
    asm volatile("ldmatrix.sync.aligned.m8n8.x2.shared.b16 {%0,%1}, [%2];"
                 : "=r"(r0), "=r"(r1) : "r"(addr));
}
__device__ __forceinline__ void mma16816(float* c, const u32* a, const u32* b) {
    asm volatile(
        "mma.sync.aligned.m16n8k16.row.col.f32.bf16.bf16.f32 "
        "{%0,%1,%2,%3}, {%4,%5,%6,%7}, {%8,%9}, {%0,%1,%2,%3};"
        : "+f"(c[0]), "+f"(c[1]), "+f"(c[2]), "+f"(c[3])
        : "r"(a[0]), "r"(a[1]), "r"(a[2]), "r"(a[3]), "r"(b[0]), "r"(b[1]));
}

// ---------------- CSR build ----------------
__global__ void k_zero_cnt() {
    int i = blockIdx.x * blockDim.x + threadIdx.x;
    if (i < NN) g_cnt[i] = 0;
}
__global__ void k_count(const int* __restrict__ src) {
    int e = blockIdx.x * blockDim.x + threadIdx.x;
    if (e < NE) atomicAdd(&g_cnt[src[e]], 1);
}
__global__ void k_scan() {
    __shared__ int part[1024];
    int t = threadIdx.x;
    const int CH = (NN + 1023) / 1024;
    int base = t * CH;
    int s = 0;
    for (int i = 0; i < CH; i++) {
        int idx = base + i;
        if (idx < NN) s += g_cnt[idx];
    }
    part[t] = s;
    __syncthreads();
    for (int d = 1; d < 1024; d <<= 1) {
        int v = (t >= d) ? part[t - d] : 0;
        __syncthreads();
        part[t] += v;
        __syncthreads();
    }
    int pre = (t == 0) ? 0 : part[t - 1];
    for (int i = 0; i < CH; i++) {
        int idx = base + i;
        if (idx < NN) {
            g_off[idx] = pre;
            g_cur[idx] = pre;
            pre += g_cnt[idx];
        }
    }
    if (t == 1023) g_off[NN] = part[1023];
}
__global__ void k_scatter(const int* __restrict__ src) {
    int e = blockIdx.x * blockDim.x + threadIdx.x;
    if (e < NE) {
        int p = atomicAdd(&g_cur[src[e]], 1);
        g_perm[p] = e;
    }
}

// ---------------- W2 split+transpose: g_Wbf[n][j], blocks [hi | lo | hi] ----------------
__global__ void k_wsplit(const float* __restrict__ w2, int K) {
    int p = blockIdx.x * blockDim.x + threadIdx.x;
    if (p >= 8192 * 192) return;
    int n = p / 192, j = p - n * 192;
    int b = j >> 6, k = j & 63;
    int c = n >> 6, o = n & 63;
    float v = (k < K) ? w2[(size_t)c * (K * 64) + k * 64 + o] : 0.f;
    __nv_bfloat16 hi = __float2bfloat16(v);
    __nv_bfloat16 outv = hi;
    if (b == 1) outv = __float2bfloat16(v - __bfloat162float(hi));
    g_Wbf[p] = outv;
}

// ---------------- edge hidden ----------------
#define EPC 25
__global__ void k_edge_h(const float* __restrict__ ea,
                         const float* __restrict__ w1,
                         const float* __restrict__ b1) {
    __shared__ float ws[EIN * 128];
    __shared__ float bs[128];
    __shared__ float eas[EIN];
    int c = threadIdx.x;
    for (int i = 0; i < EIN; i++) ws[i * 128 + c] = w1[i * 128 + c];
    bs[c] = b1[c];
    int e0 = blockIdx.x * EPC;
    int e1 = min(e0 + EPC, NE);
    for (int e = e0; e < e1; e++) {
        __syncthreads();
        if (c < EIN) eas[c] = ea[(size_t)e * EIN + c];
        __syncthreads();
        float s = bs[c];
#pragma unroll
        for (int i = 0; i < EIN; i++) s += eas[i] * ws[i * 128 + c];
        g_H[(size_t)e * 128 + c] = fmaxf(s, 0.f);
    }
}

// ---------------- node pre ----------------
__global__ void k_node_pre(const float* __restrict__ x, int C,
                           const float* __restrict__ root,
                           const float* __restrict__ bias,
                           const float* __restrict__ b2) {
    __shared__ float xs[4][64];
    __shared__ float rs[64 * 64];
    __shared__ float b2s[64 * 64];
    int t = threadIdx.x;
    int o = t & 63, s = t >> 6;
    for (int i = t; i < C * 64; i += 256) { rs[i] = root[i]; b2s[i] = b2[i]; }
    int n = blockIdx.x * 4 + s;
    if (n < NN) {
        for (int k = o; k < C; k += 64) xs[s][k] = x[(size_t)n * C + k];
    }
    __syncthreads();
    if (n < NN) {
        float a = bias[o], xbv = 0.f;
        for (int k = 0; k < C; k++) {
            float xv = xs[s][k];
            a   += xv * rs [k * 64 + o];
            xbv += xv * b2s[k * 64 + o];
        }
        g_agg[n * 64 + o] = a;
        g_xb [n * 64 + o] = xbv;
    }
}

// ---------------- mma.sync Q GEMM: 128x128 tile, K'=192 hi/lo split ----------------
#define ASTRIDE 200   // bf16 elems per padded SMEM row (400 B, conflict-free for ldmatrix)

__global__ void __launch_bounds__(256, 1) k_qgemm_mma(const float* __restrict__ X, int K) {
    extern __shared__ __nv_bfloat16 smem[];
    __nv_bfloat16* As = smem;                 // 128 x ASTRIDE
    __nv_bfloat16* Bs = smem + 128 * ASTRIDE; // 128 x ASTRIDE
    int t = threadIdx.x, wid = t >> 5, lane = t & 31;
    int row0 = blockIdx.y * 128, col0 = blockIdx.x * 128;

    // ---- A fill: thread handles row r = t/2, k-half (t&1)*32; blocks [hi|hi|lo] ----
    {
        int r = t >> 1;
        int n = row0 + r;
        int kh = (t & 1) * 32;
        u32* Arow = (u32*)(As + r * ASTRIDE);
#pragma unroll
        for (int k = kh; k < kh + 32; k += 2) {
            float v0 = 0.f, v1 = 0.f;
            if (n < NN && k < K)     v0 = X[(size_t)n * K + k];
            if (n < NN && k + 1 < K) v1 = X[(size_t)n * K + k + 1];
            __nv_bfloat16 h0 = __float2bfloat16(v0);
            __nv_bfloat16 h1 = __float2bfloat16(v1);
            __nv_bfloat16 l0 = __float2bfloat16(v0 - __bfloat162float(h0));
            __nv_bfloat16 l1 = __float2bfloat16(v1 - __bfloat162float(h1));
            u32 hp = (u32)__bfloat16_as_ushort(h0) | ((u32)__bfloat16_as_ushort(h1) << 16);
            u32 lp = (u32)__bfloat16_as_ushort(l0) | ((u32)__bfloat16_as_ushort(l1) << 16);
            Arow[k >> 1]        = hp;
            Arow[(64 + k) >> 1] = hp;
            Arow[(128 + k) >> 1] = lp;
        }
    }
    // ---- B fill: copy 128 rows x 96 u32 from g_Wbf ----
    {
        const u32* Wsrc = (const u32*)g_Wbf;
        u32* Bd = (u32*)Bs;
#pragma unroll 8
        for (int i = t; i < 128 * 96; i += 256) {
            int r = i / 96, c = i - r * 96;
            Bd[r * (ASTRIDE / 2) + c] = Wsrc[(size_t)(col0 + r) * 96 + c];
        }
    }
    __syncthreads();

    // ---- warp tiling: m-group = wid&3 (32 rows), n-group = wid>>2 (64 cols) ----
    int wm = (wid & 3) * 32;
    int wn = (wid >> 2) * 64;
    u32 a_base = smem_u32(As);
    u32 b_base = smem_u32(Bs);

    float acc[2][8][4];
#pragma unroll
    for (int i = 0; i < 2; i++)
#pragma unroll
        for (int j = 0; j < 8; j++)
#pragma unroll
            for (int q = 0; q < 4; q++) acc[i][j][q] = 0.f;

#pragma unroll
    for (int ks = 0; ks < 12; ks++) {
        int k0 = ks * 16;
        u32 a[2][4];
#pragma unroll
        for (int i = 0; i < 2; i++) {
            u32 addr = a_base + (u32)(((wm + i * 16 + (lane & 15)) * ASTRIDE +
                                        k0 + ((lane >> 4) << 3)) * 2);
            ldsm_x4(a[i][0], a[i][1], a[i][2], a[i][3], addr);
        }
        u32 b[8][2];
#pragma unroll
        for (int j = 0; j < 8; j++) {
            u32 addr = b_base + (u32)(((wn + j * 8 + (lane & 7)) * ASTRIDE +
                                        k0 + ((lane >> 3) & 1) * 8) * 2);
            ldsm_x2(b[j][0], b[j][1], addr);
        }
#pragma unroll
        for (int i = 0; i < 2; i++)
#pragma unroll
            for (int j = 0; j < 8; j++)
                mma16816(acc[i][j], a[i], b[j]);
    }

    // ---- epilogue: c frag rows = lane/4 (+8), cols = (lane&3)*2 ----
#pragma unroll
    for (int i = 0; i < 2; i++) {
        int m0 = row0 + wm + i * 16 + (lane >> 2);
#pragma unroll
        for (int j = 0; j < 8; j++) {
            int col = col0 + wn + j * 8 + (lane & 3) * 2;
            if (m0 < NN) {
                float2* p = (float2*)&g_Q[(size_t)m0 * QW + col];
                *p = make_float2(acc[i][j][0], acc[i][j][1]);
            }
            if (m0 + 8 < NN) {
                float2* p = (float2*)&g_Q[(size_t)(m0 + 8) * QW + col];
                *p = make_float2(acc[i][j][2], acc[i][j][3]);
            }
        }
    }
}

// ---------------- edge messages ----------------
__global__ void k_edge_msg(const int* __restrict__ dst) {
    int n = blockIdx.x;
    int e0 = g_off[n], e1 = g_off[n + 1];
    if (e0 >= e1) return;
    int t = threadIdx.x;
    int o = t & 63, slot = t >> 6;
    __shared__ float Qs[QW];
    __shared__ float hs[2][128];
    __shared__ float xbs[64];
    for (int i = t; i < QW; i += 128) Qs[i] = g_Q[(size_t)n * QW + i];
    if (t < 64) xbs[t] = g_xb[n * 64 + t];
    for (int ei = e0; ei < e1; ei += 2) {
        int myei = ei + slot;
        int e = (myei < e1) ? g_perm[myei] : -1;
        __syncthreads();
        if (e >= 0) {
            hs[slot][o]      = g_H[(size_t)e * 128 + o];
            hs[slot][64 + o] = g_H[(size_t)e * 128 + 64 + o];
        }
        __syncthreads();
        if (e >= 0) {
            float m = xbs[o];
#pragma unroll
            for (int c = 0; c < 128; c++) m += hs[slot][c] * Qs[c * 64 + o];
            atomicAdd(&g_agg[(size_t)dst[e] * 64 + o], m);
        }
    }
}

// ---------------- batch norm ----------------
__global__ void k_bn_zero() {
    int t = threadIdx.x;
    if (t < HID) { g_bnsum[t] = 0.f; g_bnsq[t] = 0.f; }
}
__global__ void k_bn_stats() {
    int t = threadIdx.x;
    int o = t & 63, s = t >> 6;
    float sum = 0.f, sq = 0.f;
    for (int n = blockIdx.x * 4 + s; n < NN; n += gridDim.x * 4) {
        float v = g_agg[(size_t)n * 64 + o];
        sum += v; sq += v * v;
    }
    __shared__ float ssum[256], ssq[256];
    ssum[t] = sum; ssq[t] = sq;
    __syncthreads();
    if (t < 128) { ssum[t] += ssum[t + 128]; ssq[t] += ssq[t + 128]; }
    __syncthreads();
    if (t < 64) {
        atomicAdd(&g_bnsum[t], ssum[t] + ssum[t + 64]);
        atomicAdd(&g_bnsq [t], ssq [t] + ssq [t + 64]);
    }
}
__global__ void k_bn_apply(const float* __restrict__ gamma,
                           const float* __restrict__ beta,
                           float* __restrict__ xout) {
    int i = blockIdx.x * blockDim.x + threadIdx.x;
    if (i >= NN * 64) return;
    int o = i & 63;
    float mu  = g_bnsum[o] * (1.f / NN);
    float var = g_bnsq[o] * (1.f / NN) - mu * mu;
    float v = gamma[o] * (g_agg[i] - mu) * rsqrtf(var + EPS_BN) + beta[o];
    xout[i] = fmaxf(v, 0.f);
}

// ---------------- pooling + final MLP ----------------
__global__ void k_pool_init() {
    int i = blockIdx.x * blockDim.x + threadIdx.x;
    if (i < NG * HID) g_pool[i] = 0.f;
}
__global__ void k_pool(const float* __restrict__ xl, const int* __restrict__ batch) {
    int i = blockIdx.x * blockDim.x + threadIdx.x;
    if (i >= NN * 64) return;
    int n = i >> 6, o = i & 63;
    int g = batch[n];
    atomicMax(reinterpret_cast<unsigned int*>(&g_pool[g * 64 + o]), __float_as_uint(xl[i]));
}
__global__ void k_final(const float* __restrict__ u,
                        const float* __restrict__ w1, const float* __restrict__ b1,
                        const float* __restrict__ w2, const float* __restrict__ b2,
                        float* __restrict__ out) {
    int g = blockIdx.x;
    int j = threadIdx.x;
    __shared__ float cat[72];
    __shared__ float red[64];
    if (j < 64) cat[j] = g_pool[g * 64 + j];
    if (j < 8)  cat[64 + j] = u[g * 8 + j];
    __syncthreads();
    float h = b1[j];
#pragma unroll
    for (int k = 0; k < 72; k++) h += cat[k] * w1[k * 64 + j];
    h = fmaxf(h, 0.f);
    red[j] = h * w2[j];
    __syncthreads();
    for (int s = 32; s > 0; s >>= 1) {
        if (j < s) red[j] += red[j + s];
        __syncthreads();
    }
    if (j == 0) out[g] = red[0] + b2[0];
}

// ---------------- host ----------------
extern "C" void kernel_launch(void* const* d_in, const int* in_sizes, int n_in,
                              void* d_out, int out_size) {
    const float* x       = (const float*)d_in[0];
    const int*   ei      = (const int*)  d_in[1];
    const float* ea      = (const float*)d_in[2];
    const int*   batch   = (const int*)  d_in[3];
    const float* u       = (const float*)d_in[4];
    const float* enn0_w1 = (const float*)d_in[5];
    const float* enn0_b1 = (const float*)d_in[6];
    const float* enn0_w2 = (const float*)d_in[7];
    const float* enn0_b2 = (const float*)d_in[8];
    const float* root0   = (const float*)d_in[9];
    const float* bias0   = (const float*)d_in[10];
    const float* gamma0  = (const float*)d_in[11];
    const float* beta0   = (const float*)d_in[12];
    const float* enn_w1  = (const float*)d_in[13];
    const float* enn_b1  = (const float*)d_in[14];
    const float* enn_w2  = (const float*)d_in[15];
    const float* enn_b2  = (const float*)d_in[16];
    const float* root_l  = (const float*)d_in[17];
    const float* bias_l  = (const float*)d_in[18];
    const float* gamma_l = (const float*)d_in[19];
    const float* beta_l  = (const float*)d_in[20];
    const float* pp_w1   = (const float*)d_in[21];
    const float* pp_b1   = (const float*)d_in[22];
    const float* pp_w2   = (const float*)d_in[23];
    const float* pp_b2   = (const float*)d_in[24];

    const int* src  = ei;
    const int* dste = ei + NE;

    const int QG_SMEM = 2 * 128 * ASTRIDE * 2;  // 102400 B
    cudaFuncSetAttribute(k_qgemm_mma, cudaFuncAttributeMaxDynamicSharedMemorySize, QG_SMEM);

    void* pA; cudaGetSymbolAddress(&pA, g_xA);
    void* pB; cudaGetSymbolAddress(&pB, g_xB);
    float* xA = (float*)pA;
    float* xB = (float*)pB;

    k_zero_cnt<<<(NN + 255) / 256, 256>>>();
    k_count  <<<(NE + 255) / 256, 256>>>(src);
    k_scan   <<<1, 1024>>>();
    k_scatter<<<(NE + 255) / 256, 256>>>(src);

    const float* xin = x;
    int C = IN_CH;
    float* xout = xA;

    for (int l = 0; l < 4; l++) {
        const float *w1, *b1, *w2, *b2, *rt, *bs, *gm, *bt;
        if (l == 0) {
            w1 = enn0_w1; b1 = enn0_b1; w2 = enn0_w2; b2 = enn0_b2;
            rt = root0; bs = bias0; gm = gamma0; bt = beta0;
        } else {
            int m = l - 1;
            w1 = enn_w1 + (size_t)m * EIN * 128;
            b1 = enn_b1 + (size_t)m * 128;
            w2 = enn_w2 + (size_t)m * 128 * 4096;
            b2 = enn_b2 + (size_t)m * 4096;
            rt = root_l + (size_t)m * 64 * 64;
            bs = bias_l + (size_t)m * 64;
            gm = gamma_l + (size_t)m * 64;
            bt = beta_l + (size_t)m * 64;
        }
        k_wsplit  <<<(8192 * 192 + 255) / 256, 256>>>(w2, C);
        k_edge_h  <<<(NE + EPC - 1) / EPC, 128>>>(ea, w1, b1);
        k_node_pre<<<(NN + 3) / 4, 256>>>(xin, C, rt, bs, b2);
        dim3 gq(QW / 128, (NN + 127) / 128);
        k_qgemm_mma<<<gq, 256, QG_SMEM>>>(xin, C);
        k_edge_msg<<<NN, 128>>>(dste);
        k_bn_zero <<<1, 64>>>();
        k_bn_stats<<<128, 256>>>();
        k_bn_apply<<<(NN * 64 + 255) / 256, 256>>>(gm, bt, xout);

        xin = xout;
        C = HID;
        xout = (xout == xA) ? xB : xA;
    }

    k_pool_init<<<(NG * HID + 255) / 256, 256>>>();
    k_pool     <<<(NN * 64 + 255) / 256, 256>>>(xin, batch);
    k_final    <<<NG, 64>>>(u, pp_w1, pp_b1, pp_w2, pp_b2, (float*)d_out);
}